// round 1
// baseline (speedup 1.0000x reference)
#include <cuda_runtime.h>

#define EMBED   1024
#define NHEAD   16
#define HD      64
#define SEQ     2048
#define BATCH   4
#define MROWS   (BATCH * SEQ)      /* 8192 */
#define QKVN    (3 * EMBED)        /* 3072 */

// Scratch (device globals -- runtime allocation is forbidden)
static __device__ float g_qkv[(size_t)MROWS * QKVN];   // 96 MB
static __device__ float g_att[(size_t)MROWS * EMBED];  // 32 MB

// ---------------------------------------------------------------------------
// Generic fp32 GEMM: C[M,N] = A[M,K] @ B[K,N] + bias[N]
// BM=BN=128, BK=16, 256 threads, 8x8 micro-tile per thread.
// M, N multiples of 128; K multiple of 16 (true for all uses here).
// ---------------------------------------------------------------------------
__global__ __launch_bounds__(256) void sgemm_bias(
    const float* __restrict__ A, const float* __restrict__ B,
    const float* __restrict__ bias, float* __restrict__ C,
    int N, int K)
{
    __shared__ float As[16][128];   // As[k][m] (transposed)
    __shared__ float Bs[16][128];   // Bs[k][n]

    const int tid = threadIdx.x;
    const int tx = tid & 15;
    const int ty = tid >> 4;
    const int m0 = blockIdx.y * 128;
    const int n0 = blockIdx.x * 128;

    const int ar = tid >> 2;            // 0..63  (A row within tile, +64 second pass)
    const int ak = (tid & 3) << 2;      // 0,4,8,12
    const int br = tid >> 5;            // 0..7   (B k-row, +8 second pass)
    const int bc = (tid & 31) << 2;     // 0..124

    float acc[8][8];
#pragma unroll
    for (int i = 0; i < 8; i++)
#pragma unroll
        for (int j = 0; j < 8; j++) acc[i][j] = 0.f;

    const float* Ab = A + (size_t)m0 * K;

    for (int k0 = 0; k0 < K; k0 += 16) {
        float4 a0 = *(const float4*)(Ab + (size_t)ar        * K + k0 + ak);
        float4 a1 = *(const float4*)(Ab + (size_t)(ar + 64) * K + k0 + ak);
        float4 b0 = *(const float4*)(B + (size_t)(k0 + br)     * N + n0 + bc);
        float4 b1 = *(const float4*)(B + (size_t)(k0 + br + 8) * N + n0 + bc);

        __syncthreads();   // previous iteration's compute must finish before overwrite
        As[ak + 0][ar] = a0.x; As[ak + 1][ar] = a0.y;
        As[ak + 2][ar] = a0.z; As[ak + 3][ar] = a0.w;
        As[ak + 0][ar + 64] = a1.x; As[ak + 1][ar + 64] = a1.y;
        As[ak + 2][ar + 64] = a1.z; As[ak + 3][ar + 64] = a1.w;
        *(float4*)&Bs[br][bc]     = b0;
        *(float4*)&Bs[br + 8][bc] = b1;
        __syncthreads();

#pragma unroll
        for (int k = 0; k < 16; k++) {
            float a[8], b[8];
            *(float4*)&a[0] = *(const float4*)&As[k][ty << 2];
            *(float4*)&a[4] = *(const float4*)&As[k][64 + (ty << 2)];
            *(float4*)&b[0] = *(const float4*)&Bs[k][tx << 2];
            *(float4*)&b[4] = *(const float4*)&Bs[k][64 + (tx << 2)];
#pragma unroll
            for (int i = 0; i < 8; i++)
#pragma unroll
                for (int j = 0; j < 8; j++)
                    acc[i][j] = fmaf(a[i], b[j], acc[i][j]);
        }
    }

    float4 bv0 = *(const float4*)(bias + n0 + (tx << 2));
    float4 bv1 = *(const float4*)(bias + n0 + 64 + (tx << 2));
#pragma unroll
    for (int i = 0; i < 8; i++) {
        int row = m0 + ((i < 4) ? ((ty << 2) + i) : (64 + (ty << 2) + i - 4));
        float* Cp = C + (size_t)row * N + n0;
        float4 o0 = make_float4(acc[i][0] + bv0.x, acc[i][1] + bv0.y,
                                acc[i][2] + bv0.z, acc[i][3] + bv0.w);
        float4 o1 = make_float4(acc[i][4] + bv1.x, acc[i][5] + bv1.y,
                                acc[i][6] + bv1.z, acc[i][7] + bv1.w);
        *(float4*)(Cp + (tx << 2))      = o0;
        *(float4*)(Cp + 64 + (tx << 2)) = o1;
    }
}

// ---------------------------------------------------------------------------
// Flash attention (fp32): per (b, h, q-block of 64) iterate over 32 key tiles
// of 64. Q,K stored d-major (transposed) in smem with a 4-wide XOR swizzle so
// both the tile-load stores and the hot LDS.128 compute loads are conflict-
// light. V natural [k][d]; P stored [q][k] with float4 row stores.
// 256 threads = 16x16 grid; each thread owns a 4q x 4k score micro-tile and a
// 4q x 4d output micro-tile. Softmax row reductions via 16-lane shfl.
// ---------------------------------------------------------------------------
__global__ __launch_bounds__(256) void attn_kernel(
    const float* __restrict__ qkv, float* __restrict__ outp)
{
    extern __shared__ float sm[];
    float* Qt = sm;           // [64 d][64 q] swizzled
    float* Kt = sm + 4096;    // [64 d][64 k] swizzled
    float* Vs = sm + 8192;    // [64 k][64 d] natural
    float* Pt = sm + 12288;   // [64 q][64 k]

    const int tid = threadIdx.x;
    const int tx = tid & 15;
    const int ty = tid >> 4;
    const int qb = blockIdx.x;
    const int h  = blockIdx.y;
    const int b  = blockIdx.z;
    const size_t base = ((size_t)b * SEQ) * QKVN + (size_t)h * HD;
    const float scale = 0.125f;   // HD^-0.5

    // Load Q block (pre-scaled), transposed + swizzled
#pragma unroll
    for (int c = 0; c < 4; c++) {
        int fi = (c << 8) + tid;          // float4 id, 0..1023
        int r  = fi >> 4;                 // token within block
        int d0 = (fi & 15) << 2;          // feature
        float4 v = *(const float4*)(qkv + base + (size_t)(qb * 64 + r) * QKVN + d0);
        const float* vp = (const float*)&v;
#pragma unroll
        for (int x = 0; x < 4; x++) {
            int d = d0 + x;
            Qt[(d << 6) + ((((r >> 2) ^ ((d >> 2) & 15)) << 2) | (r & 3))] = vp[x] * scale;
        }
    }

    float o[4][4];
#pragma unroll
    for (int i = 0; i < 4; i++)
#pragma unroll
        for (int j = 0; j < 4; j++) o[i][j] = 0.f;
    float mrow[4] = {-1e30f, -1e30f, -1e30f, -1e30f};
    float lrow[4] = {0.f, 0.f, 0.f, 0.f};

    for (int kt = 0; kt < 32; kt++) {
        if (kt) __syncthreads();   // prior iteration done reading Kt/Vs/Pt

        // Load K (transposed+swizzled) and V (natural) tiles
#pragma unroll
        for (int c = 0; c < 4; c++) {
            int fi = (c << 8) + tid;
            int r  = fi >> 4;
            int d0 = (fi & 15) << 2;
            size_t g = base + (size_t)(kt * 64 + r) * QKVN + d0;
            float4 kv = *(const float4*)(qkv + g + 1024);
            float4 vv = *(const float4*)(qkv + g + 2048);
            const float* kp = (const float*)&kv;
#pragma unroll
            for (int x = 0; x < 4; x++) {
                int d = d0 + x;
                Kt[(d << 6) + ((((r >> 2) ^ ((d >> 2) & 15)) << 2) | (r & 3))] = kp[x];
            }
            *(float4*)&Vs[(r << 6) + d0] = vv;
        }
        __syncthreads();

        // S = Q K^T  (scaled via Q)
        float s[4][4];
#pragma unroll
        for (int i = 0; i < 4; i++)
#pragma unroll
            for (int j = 0; j < 4; j++) s[i][j] = 0.f;

#pragma unroll 8
        for (int d = 0; d < 64; d++) {
            int sz = (d >> 2) & 15;
            float4 qv = *(const float4*)&Qt[(d << 6) + ((ty ^ sz) << 2)];
            float4 kv = *(const float4*)&Kt[(d << 6) + ((tx ^ sz) << 2)];
            const float* qa = (const float*)&qv;
            const float* ka = (const float*)&kv;
#pragma unroll
            for (int i = 0; i < 4; i++)
#pragma unroll
                for (int j = 0; j < 4; j++)
                    s[i][j] = fmaf(qa[i], ka[j], s[i][j]);
        }

        // Online softmax update per q row (16-lane reduction over tx)
#pragma unroll
        for (int i = 0; i < 4; i++) {
            float rm = fmaxf(fmaxf(s[i][0], s[i][1]), fmaxf(s[i][2], s[i][3]));
            rm = fmaxf(rm, __shfl_xor_sync(0xffffffffu, rm, 1));
            rm = fmaxf(rm, __shfl_xor_sync(0xffffffffu, rm, 2));
            rm = fmaxf(rm, __shfl_xor_sync(0xffffffffu, rm, 4));
            rm = fmaxf(rm, __shfl_xor_sync(0xffffffffu, rm, 8));
            float mnew  = fmaxf(mrow[i], rm);
            float alpha = __expf(mrow[i] - mnew);
            mrow[i] = mnew;
            float p0 = __expf(s[i][0] - mnew);
            float p1 = __expf(s[i][1] - mnew);
            float p2 = __expf(s[i][2] - mnew);
            float p3 = __expf(s[i][3] - mnew);
            float rs = (p0 + p1) + (p2 + p3);
            rs += __shfl_xor_sync(0xffffffffu, rs, 1);
            rs += __shfl_xor_sync(0xffffffffu, rs, 2);
            rs += __shfl_xor_sync(0xffffffffu, rs, 4);
            rs += __shfl_xor_sync(0xffffffffu, rs, 8);
            lrow[i] = lrow[i] * alpha + rs;
            o[i][0] *= alpha; o[i][1] *= alpha; o[i][2] *= alpha; o[i][3] *= alpha;
            *(float4*)&Pt[(((ty << 2) + i) << 6) + (tx << 2)] = make_float4(p0, p1, p2, p3);
        }
        __syncthreads();   // Pt visible to all

        // O += P V
#pragma unroll 8
        for (int kk = 0; kk < 64; kk++) {
            float4 vv = *(const float4*)&Vs[(kk << 6) + (tx << 2)];
            const float* va = (const float*)&vv;
            float p0 = Pt[(((ty << 2) + 0) << 6) + kk];
            float p1 = Pt[(((ty << 2) + 1) << 6) + kk];
            float p2 = Pt[(((ty << 2) + 2) << 6) + kk];
            float p3 = Pt[(((ty << 2) + 3) << 6) + kk];
#pragma unroll
            for (int j = 0; j < 4; j++) {
                o[0][j] = fmaf(p0, va[j], o[0][j]);
                o[1][j] = fmaf(p1, va[j], o[1][j]);
                o[2][j] = fmaf(p2, va[j], o[2][j]);
                o[3][j] = fmaf(p3, va[j], o[3][j]);
            }
        }
    }

    // Normalize and write (b, t, h*64 + d) layout
#pragma unroll
    for (int i = 0; i < 4; i++) {
        float inv = 1.0f / lrow[i];
        int t = qb * 64 + (ty << 2) + i;
        float4 ov = make_float4(o[i][0] * inv, o[i][1] * inv,
                                o[i][2] * inv, o[i][3] * inv);
        *(float4*)(outp + ((size_t)(b * SEQ + t)) * EMBED + h * HD + (tx << 2)) = ov;
    }
}

// ---------------------------------------------------------------------------
extern "C" void kernel_launch(void* const* d_in, const int* in_sizes, int n_in,
                              void* d_out, int out_size)
{
    (void)in_sizes; (void)n_in; (void)out_size;
    const float* x     = (const float*)d_in[0];
    const float* w_qkv = (const float*)d_in[1];
    const float* b_qkv = (const float*)d_in[2];
    const float* w_out = (const float*)d_in[3];
    const float* b_out = (const float*)d_in[4];
    float* out = (float*)d_out;

    float *qkv_p = nullptr, *att_p = nullptr;
    cudaGetSymbolAddress((void**)&qkv_p, g_qkv);
    cudaGetSymbolAddress((void**)&att_p, g_att);

    cudaFuncSetAttribute(attn_kernel,
                         cudaFuncAttributeMaxDynamicSharedMemorySize, 65536);

    // 1) QKV projection: [8192,1024] @ [1024,3072] + b
    sgemm_bias<<<dim3(QKVN / 128, MROWS / 128), 256>>>(x, w_qkv, b_qkv, qkv_p,
                                                       QKVN, EMBED);
    // 2) Attention
    attn_kernel<<<dim3(SEQ / 64, NHEAD, BATCH), 256, 65536>>>(qkv_p, att_p);
    // 3) Output projection: [8192,1024] @ [1024,1024] + b
    sgemm_bias<<<dim3(EMBED / 128, MROWS / 128), 256>>>(att_p, w_out, b_out, out,
                                                        EMBED, EMBED);
}

// round 3
// speedup vs baseline: 1.2987x; 1.2987x over previous
#include <cuda_runtime.h>
#include <cuda_bf16.h>
#include <cstdint>

#define EMBED   1024
#define NHEAD   16
#define HD      64
#define SEQ     2048
#define BATCH   4
#define MROWS   (BATCH * SEQ)      /* 8192 */
#define QKVN    (3 * EMBED)        /* 3072 */
#define KDIM    1024               /* K of both projections */

// ---------------------------------------------------------------------------
// Scratch (device globals -- runtime allocation is forbidden)
// ---------------------------------------------------------------------------
static __device__ float g_qkv[(size_t)MROWS * QKVN];               // 96 MB fp32
static __device__ float g_att[(size_t)MROWS * EMBED];              // 32 MB fp32
static __device__ __nv_bfloat16 g_x2  [(size_t)MROWS * 2 * KDIM];  // A' gemm1
static __device__ __nv_bfloat16 g_att2[(size_t)MROWS * 2 * KDIM];  // A' gemm2
static __device__ __nv_bfloat16 g_wq2 [(size_t)QKVN  * 2 * KDIM];  // B' gemm1
static __device__ __nv_bfloat16 g_wo2 [(size_t)EMBED * 2 * KDIM];  // B' gemm2

// ---------------------------------------------------------------------------
// Small PTX helpers (baseline ISA only -- sm_80+; no arch-conditional ops)
// ---------------------------------------------------------------------------
__device__ __forceinline__ uint32_t smem_u32(const void* p) {
    uint32_t a;
    asm("{ .reg .u64 t; cvta.to.shared.u64 t, %1; cvt.u32.u64 %0, t; }"
        : "=r"(a) : "l"(p));
    return a;
}

__device__ __forceinline__ void cpasync16(uint32_t dst, const void* src) {
    asm volatile("cp.async.cg.shared.global [%0], [%1], 16;"
        :: "r"(dst), "l"(src) : "memory");
}
#define CP_COMMIT() asm volatile("cp.async.commit_group;" ::: "memory")

__device__ __forceinline__ void ldsm4(uint32_t* r, uint32_t addr) {
    asm volatile("ldmatrix.sync.aligned.m8n8.x4.shared.b16 {%0,%1,%2,%3}, [%4];"
        : "=r"(r[0]), "=r"(r[1]), "=r"(r[2]), "=r"(r[3]) : "r"(addr));
}

__device__ __forceinline__ void mma16816(float* c, const uint32_t* a,
                                         uint32_t b0, uint32_t b1) {
    asm volatile(
        "mma.sync.aligned.m16n8k16.row.col.f32.bf16.bf16.f32 "
        "{%0,%1,%2,%3}, {%4,%5,%6,%7}, {%8,%9}, {%0,%1,%2,%3};"
        : "+f"(c[0]), "+f"(c[1]), "+f"(c[2]), "+f"(c[3])
        : "r"(a[0]), "r"(a[1]), "r"(a[2]), "r"(a[3]), "r"(b0), "r"(b1));
}

// ---------------------------------------------------------------------------
// bf16 hi/lo split kernels
// ---------------------------------------------------------------------------
__device__ __forceinline__ void split1(float v, __nv_bfloat16& h, __nv_bfloat16& l) {
    h = __float2bfloat16(v);
    l = __float2bfloat16(v - __bfloat162float(h));
}

// in [M, K] fp32 -> out [M, 2K] bf16 : [hi(0..K-1) | lo(0..K-1)]
__global__ void split_rows(const float* __restrict__ in, __nv_bfloat16* __restrict__ out) {
    size_t i4 = (size_t)blockIdx.x * blockDim.x + threadIdx.x;
    size_t row = i4 / (KDIM / 4);
    int    c   = (int)(i4 % (KDIM / 4)) << 2;
    float4 v = *(const float4*)(in + row * KDIM + c);
    __nv_bfloat16 h0, h1, h2, h3, l0, l1, l2, l3;
    split1(v.x, h0, l0); split1(v.y, h1, l1); split1(v.z, h2, l2); split1(v.w, h3, l3);
    __nv_bfloat16* oh = out + row * (2 * KDIM) + c;
    __nv_bfloat16* ol = oh + KDIM;
    *(__nv_bfloat162*)(oh)     = __nv_bfloat162(h0, h1);
    *(__nv_bfloat162*)(oh + 2) = __nv_bfloat162(h2, h3);
    *(__nv_bfloat162*)(ol)     = __nv_bfloat162(l0, l1);
    *(__nv_bfloat162*)(ol + 2) = __nv_bfloat162(l2, l3);
}

// w [K, N] fp32 -> out [N, 2K] bf16 (transpose + split)
__global__ __launch_bounds__(256) void split_wT(const float* __restrict__ w,
                                                __nv_bfloat16* __restrict__ out, int N) {
    __shared__ float t[32][33];
    const int tid = threadIdx.x;
    const int tx = tid & 31, ty = tid >> 5;
    const int n0 = blockIdx.x * 32, k0 = blockIdx.y * 32;
#pragma unroll
    for (int i = 0; i < 4; i++)
        t[ty + 8 * i][tx] = w[(size_t)(k0 + ty + 8 * i) * N + n0 + tx];
    __syncthreads();
#pragma unroll
    for (int i = 0; i < 4; i++) {
        int nl = ty + 8 * i;
        float v = t[tx][nl];
        __nv_bfloat16 h, l; split1(v, h, l);
        __nv_bfloat16* o = out + (size_t)(n0 + nl) * (2 * KDIM) + k0 + tx;
        o[0] = h; o[KDIM] = l;
    }
}

// ---------------------------------------------------------------------------
// mma.sync bf16x3 GEMM: C[M,N] = A[M,K] @ B[K,N] + bias (fp32 in/out)
// A' [M,2K] bf16 (hi|lo), B' [N,2K] bf16 (hi|lo = w transposed).
// CTA 128x128, BK=64, 3-stage cp.async pipeline, 8 warps, warp tile 64x32.
// Per k16 step, 3 split terms: Ahi*Bhi + Alo*Bhi + Ahi*Blo.
// smem per stage: Ahi 16K | Alo 16K | Bhi 16K | Blo 16K = 64KB; rows are
// 128B, 16B chunks XOR-swizzled (c ^ (row&7)) -> conflict-free ldmatrix.
// ---------------------------------------------------------------------------
#define BM 128
#define BN 128
#define BK 64
#define NK (KDIM / BK)            /* 16 */
#define NSTAGE 3
#define STG_BYTES 65536
#define GEMM_SMEM (NSTAGE * STG_BYTES)   /* 196608 */

__device__ __forceinline__ void gemm_load_stage(
    uint32_t sbase, const __nv_bfloat16* __restrict__ A2,
    const __nv_bfloat16* __restrict__ B2, int m0, int n0, int kt, int tid)
{
    const int k0 = kt * BK;
#pragma unroll
    for (int i = 0; i < 4; i++) {
        int id = tid + 256 * i;        // 0..1023
        int row = id >> 3;
        int c   = id & 7;
        uint32_t soff = row * 128 + ((c ^ (row & 7)) << 4);
        const __nv_bfloat16* ga = A2 + (size_t)(m0 + row) * (2 * KDIM) + k0 + c * 8;
        cpasync16(sbase + soff,          ga);          // A hi
        cpasync16(sbase + 16384 + soff,  ga + KDIM);   // A lo
        const __nv_bfloat16* gb = B2 + (size_t)(n0 + row) * (2 * KDIM) + k0 + c * 8;
        cpasync16(sbase + 32768 + soff,  gb);          // B hi
        cpasync16(sbase + 49152 + soff,  gb + KDIM);   // B lo
    }
}

__global__ __launch_bounds__(256, 1) void mma_gemm(
    const __nv_bfloat16* __restrict__ A2, const __nv_bfloat16* __restrict__ B2,
    const float* __restrict__ bias, float* __restrict__ C, int N)
{
    extern __shared__ char sm[];
    const uint32_t sb = smem_u32(sm);
    const int tid  = threadIdx.x;
    const int lane = tid & 31;
    const int wid  = tid >> 5;
    const int wm   = wid & 1;          // 2 warps over M
    const int wn   = wid >> 1;         // 4 warps over N
    const int m0 = blockIdx.y * BM;
    const int n0 = blockIdx.x * BN;

    const int lrow  = lane & 15;
    const int lhalf = lane >> 4;
    const int xorv  = lrow & 7;

    // per-lane smem row byte offsets for ldmatrix tiles
    uint32_t arow[4], brow[2];
#pragma unroll
    for (int mt = 0; mt < 4; mt++) arow[mt] = (wm * 64 + mt * 16 + lrow) * 128;
#pragma unroll
    for (int nt2 = 0; nt2 < 2; nt2++) brow[nt2] = (wn * 32 + nt2 * 16 + lrow) * 128;

    float acc[4][4][4];
#pragma unroll
    for (int i = 0; i < 4; i++)
#pragma unroll
        for (int j = 0; j < 4; j++)
#pragma unroll
            for (int q = 0; q < 4; q++) acc[i][j][q] = 0.f;

    // prologue: stages 0,1
    gemm_load_stage(sb,             A2, B2, m0, n0, 0, tid); CP_COMMIT();
    gemm_load_stage(sb + STG_BYTES, A2, B2, m0, n0, 1, tid); CP_COMMIT();

    for (int kt = 0; kt < NK; kt++) {
        if (kt < NK - 2) {
            gemm_load_stage(sb + ((kt + 2) % NSTAGE) * STG_BYTES, A2, B2, m0, n0, kt + 2, tid);
            CP_COMMIT();
            asm volatile("cp.async.wait_group 2;" ::: "memory");
        } else if (kt == NK - 2) {
            asm volatile("cp.async.wait_group 1;" ::: "memory");
        } else {
            asm volatile("cp.async.wait_group 0;" ::: "memory");
        }
        __syncthreads();

        const uint32_t st = sb + (kt % NSTAGE) * STG_BYTES;
#pragma unroll
        for (int ks = 0; ks < 4; ks++) {
            const uint32_t coff = (uint32_t)(((ks * 2 + lhalf) ^ xorv) << 4);
            uint32_t ah[4][4], al[4][4], bh[2][4], bl[2][4];
#pragma unroll
            for (int mt = 0; mt < 4; mt++) {
                ldsm4(ah[mt], st + arow[mt] + coff);
                ldsm4(al[mt], st + 16384 + arow[mt] + coff);
            }
#pragma unroll
            for (int nt2 = 0; nt2 < 2; nt2++) {
                ldsm4(bh[nt2], st + 32768 + brow[nt2] + coff);
                ldsm4(bl[nt2], st + 49152 + brow[nt2] + coff);
            }
#pragma unroll
            for (int mt = 0; mt < 4; mt++)
#pragma unroll
                for (int nt = 0; nt < 4; nt++) {
                    const int n2 = nt >> 1, sel = nt & 1;
                    mma16816(acc[mt][nt], ah[mt], bh[n2][sel], bh[n2][sel + 2]);
                    mma16816(acc[mt][nt], al[mt], bh[n2][sel], bh[n2][sel + 2]);
                    mma16816(acc[mt][nt], ah[mt], bl[n2][sel], bl[n2][sel + 2]);
                }
        }
        __syncthreads();
    }

    // epilogue: bias + store
#pragma unroll
    for (int nt = 0; nt < 4; nt++) {
        const int col = n0 + wn * 32 + nt * 8 + (lane & 3) * 2;
        const float bx = __ldg(bias + col);
        const float by = __ldg(bias + col + 1);
#pragma unroll
        for (int mt = 0; mt < 4; mt++) {
            const int row = m0 + wm * 64 + mt * 16 + (lane >> 2);
            float2 v0 = make_float2(acc[mt][nt][0] + bx, acc[mt][nt][1] + by);
            float2 v1 = make_float2(acc[mt][nt][2] + bx, acc[mt][nt][3] + by);
            *(float2*)(C + (size_t)row * N + col)       = v0;
            *(float2*)(C + (size_t)(row + 8) * N + col) = v1;
        }
    }
}

// ---------------------------------------------------------------------------
// Flash attention (fp32) -- unchanged from R1 (passing baseline)
// ---------------------------------------------------------------------------
__global__ __launch_bounds__(256) void attn_kernel(
    const float* __restrict__ qkv, float* __restrict__ outp)
{
    extern __shared__ float smf[];
    float* Qt = smf;           // [64 d][64 q] swizzled
    float* Kt = smf + 4096;    // [64 d][64 k] swizzled
    float* Vs = smf + 8192;    // [64 k][64 d] natural
    float* Pt = smf + 12288;   // [64 q][64 k]

    const int tid = threadIdx.x;
    const int tx = tid & 15;
    const int ty = tid >> 4;
    const int qb = blockIdx.x;
    const int h  = blockIdx.y;
    const int b  = blockIdx.z;
    const size_t base = ((size_t)b * SEQ) * QKVN + (size_t)h * HD;
    const float scale = 0.125f;

#pragma unroll
    for (int c = 0; c < 4; c++) {
        int fi = (c << 8) + tid;
        int r  = fi >> 4;
        int d0 = (fi & 15) << 2;
        float4 v = *(const float4*)(qkv + base + (size_t)(qb * 64 + r) * QKVN + d0);
        const float* vp = (const float*)&v;
#pragma unroll
        for (int x = 0; x < 4; x++) {
            int d = d0 + x;
            Qt[(d << 6) + ((((r >> 2) ^ ((d >> 2) & 15)) << 2) | (r & 3))] = vp[x] * scale;
        }
    }

    float o[4][4];
#pragma unroll
    for (int i = 0; i < 4; i++)
#pragma unroll
        for (int j = 0; j < 4; j++) o[i][j] = 0.f;
    float mrow[4] = {-1e30f, -1e30f, -1e30f, -1e30f};
    float lrow[4] = {0.f, 0.f, 0.f, 0.f};

    for (int kt = 0; kt < 32; kt++) {
        if (kt) __syncthreads();
#pragma unroll
        for (int c = 0; c < 4; c++) {
            int fi = (c << 8) + tid;
            int r  = fi >> 4;
            int d0 = (fi & 15) << 2;
            size_t g = base + (size_t)(kt * 64 + r) * QKVN + d0;
            float4 kv = *(const float4*)(qkv + g + 1024);
            float4 vv = *(const float4*)(qkv + g + 2048);
            const float* kp = (const float*)&kv;
#pragma unroll
            for (int x = 0; x < 4; x++) {
                int d = d0 + x;
                Kt[(d << 6) + ((((r >> 2) ^ ((d >> 2) & 15)) << 2) | (r & 3))] = kp[x];
            }
            *(float4*)&Vs[(r << 6) + d0] = vv;
        }
        __syncthreads();

        float s[4][4];
#pragma unroll
        for (int i = 0; i < 4; i++)
#pragma unroll
            for (int j = 0; j < 4; j++) s[i][j] = 0.f;

#pragma unroll 8
        for (int d = 0; d < 64; d++) {
            int sz = (d >> 2) & 15;
            float4 qv = *(const float4*)&Qt[(d << 6) + ((ty ^ sz) << 2)];
            float4 kv = *(const float4*)&Kt[(d << 6) + ((tx ^ sz) << 2)];
            const float* qa = (const float*)&qv;
            const float* ka = (const float*)&kv;
#pragma unroll
            for (int i = 0; i < 4; i++)
#pragma unroll
                for (int j = 0; j < 4; j++)
                    s[i][j] = fmaf(qa[i], ka[j], s[i][j]);
        }

#pragma unroll
        for (int i = 0; i < 4; i++) {
            float rm = fmaxf(fmaxf(s[i][0], s[i][1]), fmaxf(s[i][2], s[i][3]));
            rm = fmaxf(rm, __shfl_xor_sync(0xffffffffu, rm, 1));
            rm = fmaxf(rm, __shfl_xor_sync(0xffffffffu, rm, 2));
            rm = fmaxf(rm, __shfl_xor_sync(0xffffffffu, rm, 4));
            rm = fmaxf(rm, __shfl_xor_sync(0xffffffffu, rm, 8));
            float mnew  = fmaxf(mrow[i], rm);
            float alpha = __expf(mrow[i] - mnew);
            mrow[i] = mnew;
            float p0 = __expf(s[i][0] - mnew);
            float p1 = __expf(s[i][1] - mnew);
            float p2 = __expf(s[i][2] - mnew);
            float p3 = __expf(s[i][3] - mnew);
            float rs = (p0 + p1) + (p2 + p3);
            rs += __shfl_xor_sync(0xffffffffu, rs, 1);
            rs += __shfl_xor_sync(0xffffffffu, rs, 2);
            rs += __shfl_xor_sync(0xffffffffu, rs, 4);
            rs += __shfl_xor_sync(0xffffffffu, rs, 8);
            lrow[i] = lrow[i] * alpha + rs;
            o[i][0] *= alpha; o[i][1] *= alpha; o[i][2] *= alpha; o[i][3] *= alpha;
            *(float4*)&Pt[(((ty << 2) + i) << 6) + (tx << 2)] = make_float4(p0, p1, p2, p3);
        }
        __syncthreads();

#pragma unroll 8
        for (int kk = 0; kk < 64; kk++) {
            float4 vv = *(const float4*)&Vs[(kk << 6) + (tx << 2)];
            const float* va = (const float*)&vv;
            float p0 = Pt[(((ty << 2) + 0) << 6) + kk];
            float p1 = Pt[(((ty << 2) + 1) << 6) + kk];
            float p2 = Pt[(((ty << 2) + 2) << 6) + kk];
            float p3 = Pt[(((ty << 2) + 3) << 6) + kk];
#pragma unroll
            for (int j = 0; j < 4; j++) {
                o[0][j] = fmaf(p0, va[j], o[0][j]);
                o[1][j] = fmaf(p1, va[j], o[1][j]);
                o[2][j] = fmaf(p2, va[j], o[2][j]);
                o[3][j] = fmaf(p3, va[j], o[3][j]);
            }
        }
    }

#pragma unroll
    for (int i = 0; i < 4; i++) {
        float inv = 1.0f / lrow[i];
        int t = qb * 64 + (ty << 2) + i;
        float4 ov = make_float4(o[i][0] * inv, o[i][1] * inv,
                                o[i][2] * inv, o[i][3] * inv);
        *(float4*)(outp + ((size_t)(b * SEQ + t)) * EMBED + h * HD + (tx << 2)) = ov;
    }
}

// ---------------------------------------------------------------------------
// Host side
// ---------------------------------------------------------------------------
extern "C" void kernel_launch(void* const* d_in, const int* in_sizes, int n_in,
                              void* d_out, int out_size)
{
    (void)in_sizes; (void)n_in; (void)out_size;
    const float* x     = (const float*)d_in[0];
    const float* w_qkv = (const float*)d_in[1];
    const float* b_qkv = (const float*)d_in[2];
    const float* w_out = (const float*)d_in[3];
    const float* b_out = (const float*)d_in[4];
    float* out = (float*)d_out;

    float *qkv_p, *att_p;
    __nv_bfloat16 *x2, *att2, *wq2, *wo2;
    cudaGetSymbolAddress((void**)&qkv_p, g_qkv);
    cudaGetSymbolAddress((void**)&att_p, g_att);
    cudaGetSymbolAddress((void**)&x2,   g_x2);
    cudaGetSymbolAddress((void**)&att2, g_att2);
    cudaGetSymbolAddress((void**)&wq2,  g_wq2);
    cudaGetSymbolAddress((void**)&wo2,  g_wo2);

    cudaFuncSetAttribute(attn_kernel, cudaFuncAttributeMaxDynamicSharedMemorySize, 65536);
    cudaFuncSetAttribute(mma_gemm, cudaFuncAttributeMaxDynamicSharedMemorySize, GEMM_SMEM);

    // 1) split inputs to bf16 hi/lo
    split_rows<<<(MROWS * KDIM / 4) / 256, 256>>>(x, x2);
    split_wT<<<dim3(QKVN / 32, KDIM / 32), 256>>>(w_qkv, wq2, QKVN);
    split_wT<<<dim3(EMBED / 32, KDIM / 32), 256>>>(w_out, wo2, EMBED);

    // 2) QKV projection (HMMA bf16x3)
    mma_gemm<<<dim3(QKVN / BN, MROWS / BM), 256, GEMM_SMEM>>>(x2, wq2, b_qkv, qkv_p, QKVN);

    // 3) attention (fp32)
    attn_kernel<<<dim3(SEQ / 64, NHEAD, BATCH), 256, 65536>>>(qkv_p, att_p);

    // 4) split attention output, output projection
    split_rows<<<(MROWS * KDIM / 4) / 256, 256>>>(att_p, att2);
    mma_gemm<<<dim3(EMBED / BN, MROWS / BM), 256, GEMM_SMEM>>>(att2, wo2, b_out, out, EMBED);
}

// round 5
// speedup vs baseline: 2.6875x; 2.0694x over previous
#include <cuda_runtime.h>
#include <cuda_bf16.h>
#include <cstdint>

#define EMBED   1024
#define NHEAD   16
#define HD      64
#define SEQ     2048
#define BATCH   4
#define MROWS   (BATCH * SEQ)      /* 8192 */
#define QKVN    (3 * EMBED)        /* 3072 */
#define KDIM    1024

// ---------------------------------------------------------------------------
// Scratch (device globals -- runtime allocation is forbidden)
// ---------------------------------------------------------------------------
static __device__ __nv_bfloat16 g_x2  [(size_t)MROWS * 2 * KDIM];   // A' gemm1
static __device__ __nv_bfloat16 g_qkv2[(size_t)MROWS * 2 * QKVN];   // qkv hi|lo
static __device__ __nv_bfloat16 g_att2[(size_t)MROWS * 2 * KDIM];   // attn out hi|lo
static __device__ __nv_bfloat16 g_wq2 [(size_t)QKVN  * 2 * KDIM];   // B' gemm1
static __device__ __nv_bfloat16 g_wo2 [(size_t)EMBED * 2 * KDIM];   // B' gemm2

// ---------------------------------------------------------------------------
// PTX helpers (baseline ISA, sm_80-compatible encodings only)
// ---------------------------------------------------------------------------
__device__ __forceinline__ uint32_t smem_u32(const void* p) {
    uint32_t a;
    asm("{ .reg .u64 t; cvta.to.shared.u64 t, %1; cvt.u32.u64 %0, t; }"
        : "=r"(a) : "l"(p));
    return a;
}
__device__ __forceinline__ void cpasync16(uint32_t dst, const void* src) {
    asm volatile("cp.async.cg.shared.global [%0], [%1], 16;"
        :: "r"(dst), "l"(src) : "memory");
}
#define CP_COMMIT() asm volatile("cp.async.commit_group;" ::: "memory")

__device__ __forceinline__ void ldsm4(uint32_t* r, uint32_t addr) {
    asm volatile("ldmatrix.sync.aligned.m8n8.x4.shared.b16 {%0,%1,%2,%3}, [%4];"
        : "=r"(r[0]), "=r"(r[1]), "=r"(r[2]), "=r"(r[3]) : "r"(addr));
}
__device__ __forceinline__ void ldsm4t(uint32_t* r, uint32_t addr) {
    asm volatile("ldmatrix.sync.aligned.m8n8.x4.trans.shared.b16 {%0,%1,%2,%3}, [%4];"
        : "=r"(r[0]), "=r"(r[1]), "=r"(r[2]), "=r"(r[3]) : "r"(addr));
}
__device__ __forceinline__ void mma16816(float* c, const uint32_t* a,
                                         uint32_t b0, uint32_t b1) {
    asm volatile(
        "mma.sync.aligned.m16n8k16.row.col.f32.bf16.bf16.f32 "
        "{%0,%1,%2,%3}, {%4,%5,%6,%7}, {%8,%9}, {%0,%1,%2,%3};"
        : "+f"(c[0]), "+f"(c[1]), "+f"(c[2]), "+f"(c[3])
        : "r"(a[0]), "r"(a[1]), "r"(a[2]), "r"(a[3]), "r"(b0), "r"(b1));
}
__device__ __forceinline__ float ex2(float x) {
    float y; asm("ex2.approx.f32 %0, %1;" : "=f"(y) : "f"(x)); return y;
}

__device__ __forceinline__ void split1(float v, __nv_bfloat16& h, __nv_bfloat16& l) {
    h = __float2bfloat16(v);
    l = __float2bfloat16(v - __bfloat162float(h));
}
// split a float pair into packed-bf16x2 hi and lo words
__device__ __forceinline__ void pack_split(float x, float y, uint32_t& hi, uint32_t& lo) {
    __nv_bfloat162 h = __floats2bfloat162_rn(x, y);
    float hx = __bfloat162float(h.x), hy = __bfloat162float(h.y);
    __nv_bfloat162 l = __floats2bfloat162_rn(x - hx, y - hy);
    hi = *(uint32_t*)&h; lo = *(uint32_t*)&l;
}

// ---------------------------------------------------------------------------
// split kernels (GEMM operand prep)
// ---------------------------------------------------------------------------
__global__ void split_rows(const float* __restrict__ in, __nv_bfloat16* __restrict__ out) {
    size_t i4 = (size_t)blockIdx.x * blockDim.x + threadIdx.x;
    size_t row = i4 / (KDIM / 4);
    int    c   = (int)(i4 % (KDIM / 4)) << 2;
    float4 v = *(const float4*)(in + row * KDIM + c);
    __nv_bfloat16 h0, h1, h2, h3, l0, l1, l2, l3;
    split1(v.x, h0, l0); split1(v.y, h1, l1); split1(v.z, h2, l2); split1(v.w, h3, l3);
    __nv_bfloat16* oh = out + row * (2 * KDIM) + c;
    __nv_bfloat16* ol = oh + KDIM;
    *(__nv_bfloat162*)(oh)     = __nv_bfloat162(h0, h1);
    *(__nv_bfloat162*)(oh + 2) = __nv_bfloat162(h2, h3);
    *(__nv_bfloat162*)(ol)     = __nv_bfloat162(l0, l1);
    *(__nv_bfloat162*)(ol + 2) = __nv_bfloat162(l2, l3);
}

__global__ __launch_bounds__(256) void split_wT(const float* __restrict__ w,
                                                __nv_bfloat16* __restrict__ out, int N) {
    __shared__ float t[32][33];
    const int tid = threadIdx.x;
    const int tx = tid & 31, ty = tid >> 5;
    const int n0 = blockIdx.x * 32, k0 = blockIdx.y * 32;
#pragma unroll
    for (int i = 0; i < 4; i++)
        t[ty + 8 * i][tx] = w[(size_t)(k0 + ty + 8 * i) * N + n0 + tx];
    __syncthreads();
#pragma unroll
    for (int i = 0; i < 4; i++) {
        int nl = ty + 8 * i;
        float v = t[tx][nl];
        __nv_bfloat16 h, l; split1(v, h, l);
        __nv_bfloat16* o = out + (size_t)(n0 + nl) * (2 * KDIM) + k0 + tx;
        o[0] = h; o[KDIM] = l;
    }
}

// ---------------------------------------------------------------------------
// mma.sync bf16x3 GEMM (as R3), templated epilogue:
//   SPLIT=false: C fp32 [M,ldc] + bias
//   SPLIT=true : C bf16 [M,ldc], hi at col, lo at col+3072, + bias
// ---------------------------------------------------------------------------
#define BM 128
#define BN 128
#define BK 64
#define NK (KDIM / BK)
#define NSTAGE 3
#define STG_BYTES 65536
#define GEMM_SMEM (NSTAGE * STG_BYTES)

__device__ __forceinline__ void gemm_load_stage(
    uint32_t sbase, const __nv_bfloat16* __restrict__ A2,
    const __nv_bfloat16* __restrict__ B2, int m0, int n0, int kt, int tid)
{
    const int k0 = kt * BK;
#pragma unroll
    for (int i = 0; i < 4; i++) {
        int id = tid + 256 * i;
        int row = id >> 3;
        int c   = id & 7;
        uint32_t soff = row * 128 + ((c ^ (row & 7)) << 4);
        const __nv_bfloat16* ga = A2 + (size_t)(m0 + row) * (2 * KDIM) + k0 + c * 8;
        cpasync16(sbase + soff,          ga);
        cpasync16(sbase + 16384 + soff,  ga + KDIM);
        const __nv_bfloat16* gb = B2 + (size_t)(n0 + row) * (2 * KDIM) + k0 + c * 8;
        cpasync16(sbase + 32768 + soff,  gb);
        cpasync16(sbase + 49152 + soff,  gb + KDIM);
    }
}

template<bool SPLIT>
__global__ __launch_bounds__(256, 1) void mma_gemm(
    const __nv_bfloat16* __restrict__ A2, const __nv_bfloat16* __restrict__ B2,
    const float* __restrict__ bias, void* __restrict__ Cv, int ldc)
{
    extern __shared__ char sm[];
    const uint32_t sb = smem_u32(sm);
    const int tid  = threadIdx.x;
    const int lane = tid & 31;
    const int wid  = tid >> 5;
    const int wm   = wid & 1;
    const int wn   = wid >> 1;
    const int m0 = blockIdx.y * BM;
    const int n0 = blockIdx.x * BN;

    const int lrow  = lane & 15;
    const int lhalf = lane >> 4;
    const int xorv  = lrow & 7;

    uint32_t arow[4], brow[2];
#pragma unroll
    for (int mt = 0; mt < 4; mt++) arow[mt] = (wm * 64 + mt * 16 + lrow) * 128;
#pragma unroll
    for (int nt2 = 0; nt2 < 2; nt2++) brow[nt2] = (wn * 32 + nt2 * 16 + lrow) * 128;

    float acc[4][4][4];
#pragma unroll
    for (int i = 0; i < 4; i++)
#pragma unroll
        for (int j = 0; j < 4; j++)
#pragma unroll
            for (int q = 0; q < 4; q++) acc[i][j][q] = 0.f;

    gemm_load_stage(sb,             A2, B2, m0, n0, 0, tid); CP_COMMIT();
    gemm_load_stage(sb + STG_BYTES, A2, B2, m0, n0, 1, tid); CP_COMMIT();

    for (int kt = 0; kt < NK; kt++) {
        if (kt < NK - 2) {
            gemm_load_stage(sb + ((kt + 2) % NSTAGE) * STG_BYTES, A2, B2, m0, n0, kt + 2, tid);
            CP_COMMIT();
            asm volatile("cp.async.wait_group 2;" ::: "memory");
        } else if (kt == NK - 2) {
            asm volatile("cp.async.wait_group 1;" ::: "memory");
        } else {
            asm volatile("cp.async.wait_group 0;" ::: "memory");
        }
        __syncthreads();

        const uint32_t st = sb + (kt % NSTAGE) * STG_BYTES;
#pragma unroll
        for (int ks = 0; ks < 4; ks++) {
            const uint32_t coff = (uint32_t)(((ks * 2 + lhalf) ^ xorv) << 4);
            uint32_t ah[4][4], al[4][4], bh[2][4], bl[2][4];
#pragma unroll
            for (int mt = 0; mt < 4; mt++) {
                ldsm4(ah[mt], st + arow[mt] + coff);
                ldsm4(al[mt], st + 16384 + arow[mt] + coff);
            }
#pragma unroll
            for (int nt2 = 0; nt2 < 2; nt2++) {
                ldsm4(bh[nt2], st + 32768 + brow[nt2] + coff);
                ldsm4(bl[nt2], st + 49152 + brow[nt2] + coff);
            }
#pragma unroll
            for (int mt = 0; mt < 4; mt++)
#pragma unroll
                for (int nt = 0; nt < 4; nt++) {
                    const int n2 = nt >> 1, sel = nt & 1;
                    mma16816(acc[mt][nt], ah[mt], bh[n2][sel], bh[n2][sel + 2]);
                    mma16816(acc[mt][nt], al[mt], bh[n2][sel], bh[n2][sel + 2]);
                    mma16816(acc[mt][nt], ah[mt], bl[n2][sel], bl[n2][sel + 2]);
                }
        }
        __syncthreads();
    }

#pragma unroll
    for (int nt = 0; nt < 4; nt++) {
        const int col = n0 + wn * 32 + nt * 8 + (lane & 3) * 2;
        const float bx = __ldg(bias + col);
        const float by = __ldg(bias + col + 1);
#pragma unroll
        for (int mt = 0; mt < 4; mt++) {
            const int row = m0 + wm * 64 + mt * 16 + (lane >> 2);
            if (SPLIT) {
                __nv_bfloat16* Cb = (__nv_bfloat16*)Cv;
                uint32_t hi, lo;
                pack_split(acc[mt][nt][0] + bx, acc[mt][nt][1] + by, hi, lo);
                __nv_bfloat16* p = Cb + (size_t)row * ldc + col;
                *(uint32_t*)p = hi; *(uint32_t*)(p + QKVN) = lo;
                pack_split(acc[mt][nt][2] + bx, acc[mt][nt][3] + by, hi, lo);
                p = Cb + (size_t)(row + 8) * ldc + col;
                *(uint32_t*)p = hi; *(uint32_t*)(p + QKVN) = lo;
            } else {
                float* C = (float*)Cv;
                float2 v0 = make_float2(acc[mt][nt][0] + bx, acc[mt][nt][1] + by);
                float2 v1 = make_float2(acc[mt][nt][2] + bx, acc[mt][nt][3] + by);
                *(float2*)(C + (size_t)row * ldc + col)       = v0;
                *(float2*)(C + (size_t)(row + 8) * ldc + col) = v1;
            }
        }
    }
}

// ---------------------------------------------------------------------------
// Tensor-core flash attention (bf16x3).
// Per CTA: 128 q-rows, one (b,h). 8 warps x 16 rows. Key tiles of 64.
// smem: Qhi 16K | Qlo 16K | 2 stages of {Khi 8K|Klo 8K|Vhi 8K|Vlo 8K}.
// qkv2 row layout: [q k v hi (3072) | q k v lo (3072)], row stride 6144.
// Output att2 [row][hi 1024 | lo 1024].
// ---------------------------------------------------------------------------
#define AT_SMEM (32768 + 2 * 32768)   /* 98304 */
#define C1 0.18033688f                /* 0.125 * log2(e) */

__device__ __forceinline__ void attn_load_kv(
    uint32_t stage, const __nv_bfloat16* __restrict__ kvb, int tid)
{
#pragma unroll
    for (int i = 0; i < 2; i++) {
        int id = tid + 256 * i;            // 0..511 -> 64 rows x 8 chunks
        int r = id >> 3, c = id & 7;
        uint32_t soff = r * 128 + ((c ^ (r & 7)) << 4);
        const __nv_bfloat16* g = kvb + (size_t)r * 6144 + c * 8;
        cpasync16(stage +         soff, g + 1024);          // K hi
        cpasync16(stage + 8192  + soff, g + 1024 + 3072);   // K lo
        cpasync16(stage + 16384 + soff, g + 2048);          // V hi
        cpasync16(stage + 24576 + soff, g + 2048 + 3072);   // V lo
    }
}

__global__ __launch_bounds__(256, 1) void attn_mma(
    const __nv_bfloat16* __restrict__ qkv2, __nv_bfloat16* __restrict__ att2)
{
    extern __shared__ char sm[];
    const uint32_t sb = smem_u32(sm);
    const uint32_t Qh = sb, Ql = sb + 16384, ST0 = sb + 32768;

    const int tid = threadIdx.x, lane = tid & 31, wid = tid >> 5;
    const int qb = blockIdx.x, h = blockIdx.y, b = blockIdx.z;
    const int lrow = lane & 15, lhalf = lane >> 4;
    const size_t rowbase = (size_t)b * SEQ;
    const __nv_bfloat16* qg  = qkv2 + (rowbase + qb * 128) * 6144 + h * 64;
    const __nv_bfloat16* kvg = qkv2 + rowbase * 6144 + h * 64;

    // Q tile loads (hi+lo)
#pragma unroll
    for (int i = 0; i < 4; i++) {
        int id = tid + 256 * i;            // 0..1023 -> 128 rows x 8 chunks
        int r = id >> 3, c = id & 7;
        uint32_t soff = r * 128 + ((c ^ (r & 7)) << 4);
        const __nv_bfloat16* g = qg + (size_t)r * 6144 + c * 8;
        cpasync16(Qh + soff, g);
        cpasync16(Ql + soff, g + 3072);
    }
    CP_COMMIT();
    attn_load_kv(ST0,         kvg,              tid); CP_COMMIT();
    attn_load_kv(ST0 + 32768, kvg + 64 * 6144,  tid); CP_COMMIT();

    // Q fragments to registers
    asm volatile("cp.async.wait_group 2;" ::: "memory");
    __syncthreads();
    uint32_t qfh[4][4], qfl[4][4];
    {
        int r = wid * 16 + lrow;
        uint32_t ro = (uint32_t)r * 128;
        int xv = r & 7;
#pragma unroll
        for (int ds = 0; ds < 4; ds++) {
            uint32_t co = (uint32_t)(((ds * 2 + lhalf) ^ xv) << 4);
            ldsm4(qfh[ds], Qh + ro + co);
            ldsm4(qfl[ds], Ql + ro + co);
        }
    }

    float oacc[8][4];
#pragma unroll
    for (int t = 0; t < 8; t++)
#pragma unroll
        for (int q = 0; q < 4; q++) oacc[t][q] = 0.f;
    float m0 = -1e30f, m1 = -1e30f, l0 = 0.f, l1 = 0.f;

    const int kxv = lrow & 7;
    for (int kt = 0; kt < 32; kt++) {
        if (kt == 31) asm volatile("cp.async.wait_group 0;" ::: "memory");
        else          asm volatile("cp.async.wait_group 1;" ::: "memory");
        __syncthreads();
        const uint32_t st = ST0 + (uint32_t)(kt & 1) * 32768;

        // ---- S = Q K^T (3-term split)
        float sacc[8][4];
#pragma unroll
        for (int t = 0; t < 8; t++)
#pragma unroll
            for (int q = 0; q < 4; q++) sacc[t][q] = 0.f;

#pragma unroll
        for (int ds = 0; ds < 4; ds++) {
            uint32_t kh[4][4], kl[4][4];
            const uint32_t co = (uint32_t)(((ds * 2 + lhalf) ^ kxv) << 4);
#pragma unroll
            for (int g = 0; g < 4; g++) {
                uint32_t a = st + (uint32_t)(g * 16 + lrow) * 128 + co;
                ldsm4(kh[g], a);
                ldsm4(kl[g], a + 8192);
            }
#pragma unroll
            for (int g = 0; g < 4; g++)
#pragma unroll
                for (int sel = 0; sel < 2; sel++) {
                    float* c = sacc[g * 2 + sel];
                    mma16816(c, qfh[ds], kh[g][sel], kh[g][sel + 2]);
                    mma16816(c, qfl[ds], kh[g][sel], kh[g][sel + 2]);
                    mma16816(c, qfh[ds], kl[g][sel], kl[g][sel + 2]);
                }
        }

        // ---- online softmax (raw logits; scale folded into exp constant)
        float mx0 = sacc[0][0], mx1 = sacc[0][2];
#pragma unroll
        for (int t = 0; t < 8; t++) {
            mx0 = fmaxf(mx0, fmaxf(sacc[t][0], sacc[t][1]));
            mx1 = fmaxf(mx1, fmaxf(sacc[t][2], sacc[t][3]));
        }
        mx0 = fmaxf(mx0, __shfl_xor_sync(0xffffffffu, mx0, 1));
        mx0 = fmaxf(mx0, __shfl_xor_sync(0xffffffffu, mx0, 2));
        mx1 = fmaxf(mx1, __shfl_xor_sync(0xffffffffu, mx1, 1));
        mx1 = fmaxf(mx1, __shfl_xor_sync(0xffffffffu, mx1, 2));
        const float mn0 = fmaxf(m0, mx0), mn1 = fmaxf(m1, mx1);
        const float a0 = ex2((m0 - mn0) * C1), a1 = ex2((m1 - mn1) * C1);
        const float mc0 = mn0 * C1, mc1 = mn1 * C1;
        float ls0 = 0.f, ls1 = 0.f;
#pragma unroll
        for (int t = 0; t < 8; t++) {
            sacc[t][0] = ex2(fmaf(sacc[t][0], C1, -mc0));
            sacc[t][1] = ex2(fmaf(sacc[t][1], C1, -mc0));
            sacc[t][2] = ex2(fmaf(sacc[t][2], C1, -mc1));
            sacc[t][3] = ex2(fmaf(sacc[t][3], C1, -mc1));
            ls0 += sacc[t][0] + sacc[t][1];
            ls1 += sacc[t][2] + sacc[t][3];
        }
        ls0 += __shfl_xor_sync(0xffffffffu, ls0, 1);
        ls0 += __shfl_xor_sync(0xffffffffu, ls0, 2);
        ls1 += __shfl_xor_sync(0xffffffffu, ls1, 1);
        ls1 += __shfl_xor_sync(0xffffffffu, ls1, 2);
        m0 = mn0; m1 = mn1;
        l0 = l0 * a0 + ls0; l1 = l1 * a1 + ls1;
#pragma unroll
        for (int t = 0; t < 8; t++) {
            oacc[t][0] *= a0; oacc[t][1] *= a0;
            oacc[t][2] *= a1; oacc[t][3] *= a1;
        }

        // ---- O += P V (3-term split; P packed in registers)
#pragma unroll
        for (int kg = 0; kg < 4; kg++) {
            uint32_t aph[4], apl[4];
            {
                const float* t0 = sacc[2 * kg];
                const float* t1 = sacc[2 * kg + 1];
                pack_split(t0[0], t0[1], aph[0], apl[0]);
                pack_split(t0[2], t0[3], aph[1], apl[1]);
                pack_split(t1[0], t1[1], aph[2], apl[2]);
                pack_split(t1[2], t1[3], aph[3], apl[3]);
            }
            const uint32_t vro = st + 16384 + (uint32_t)(kg * 16 + lrow) * 128;
#pragma unroll
            for (int dg = 0; dg < 4; dg++) {
                uint32_t vh[4], vl[4];
                uint32_t a = vro + (uint32_t)(((dg * 2 + lhalf) ^ kxv) << 4);
                ldsm4t(vh, a);
                ldsm4t(vl, a + 8192);
#pragma unroll
                for (int sel = 0; sel < 2; sel++) {
                    float* c = oacc[dg * 2 + sel];
                    // trans-load matrix order: (2*sel, 2*sel+1) = k_lo, k_hi
                    // for the d-half selected by sel.
                    mma16816(c, aph, vh[2 * sel], vh[2 * sel + 1]);
                    mma16816(c, apl, vh[2 * sel], vh[2 * sel + 1]);
                    mma16816(c, aph, vl[2 * sel], vl[2 * sel + 1]);
                }
            }
        }
        __syncthreads();
        if (kt + 2 < 32) {
            attn_load_kv(ST0 + (uint32_t)(kt & 1) * 32768,
                         kvg + (size_t)(kt + 2) * 64 * 6144, tid);
            CP_COMMIT();
        }
    }

    // ---- epilogue: normalize, split to bf16 hi/lo, store
    const float inv0 = 1.0f / l0, inv1 = 1.0f / l1;
    const size_t grow = rowbase + (size_t)qb * 128 + wid * 16 + (lane >> 2);
#pragma unroll
    for (int t = 0; t < 8; t++) {
        const int col = h * 64 + t * 8 + (lane & 3) * 2;
        uint32_t hi, lo;
        pack_split(oacc[t][0] * inv0, oacc[t][1] * inv0, hi, lo);
        __nv_bfloat16* p = att2 + grow * 2048 + col;
        *(uint32_t*)p = hi; *(uint32_t*)(p + 1024) = lo;
        pack_split(oacc[t][2] * inv1, oacc[t][3] * inv1, hi, lo);
        p = att2 + (grow + 8) * 2048 + col;
        *(uint32_t*)p = hi; *(uint32_t*)(p + 1024) = lo;
    }
}

// ---------------------------------------------------------------------------
// Host side
// ---------------------------------------------------------------------------
extern "C" void kernel_launch(void* const* d_in, const int* in_sizes, int n_in,
                              void* d_out, int out_size)
{
    (void)in_sizes; (void)n_in; (void)out_size;
    const float* x     = (const float*)d_in[0];
    const float* w_qkv = (const float*)d_in[1];
    const float* b_qkv = (const float*)d_in[2];
    const float* w_out = (const float*)d_in[3];
    const float* b_out = (const float*)d_in[4];
    float* out = (float*)d_out;

    __nv_bfloat16 *x2, *qkv2, *att2, *wq2, *wo2;
    cudaGetSymbolAddress((void**)&x2,   g_x2);
    cudaGetSymbolAddress((void**)&qkv2, g_qkv2);
    cudaGetSymbolAddress((void**)&att2, g_att2);
    cudaGetSymbolAddress((void**)&wq2,  g_wq2);
    cudaGetSymbolAddress((void**)&wo2,  g_wo2);

    cudaFuncSetAttribute(mma_gemm<true>,  cudaFuncAttributeMaxDynamicSharedMemorySize, GEMM_SMEM);
    cudaFuncSetAttribute(mma_gemm<false>, cudaFuncAttributeMaxDynamicSharedMemorySize, GEMM_SMEM);
    cudaFuncSetAttribute(attn_mma, cudaFuncAttributeMaxDynamicSharedMemorySize, AT_SMEM);

    // 1) operand prep
    split_rows<<<(MROWS * KDIM / 4) / 256, 256>>>(x, x2);
    split_wT<<<dim3(QKVN / 32, KDIM / 32), 256>>>(w_qkv, wq2, QKVN);
    split_wT<<<dim3(EMBED / 32, KDIM / 32), 256>>>(w_out, wo2, EMBED);

    // 2) QKV projection -> split bf16 qkv
    mma_gemm<true><<<dim3(QKVN / BN, MROWS / BM), 256, GEMM_SMEM>>>(
        x2, wq2, b_qkv, qkv2, 2 * QKVN);

    // 3) tensor-core flash attention -> split bf16 att
    attn_mma<<<dim3(SEQ / 128, NHEAD, BATCH), 256, AT_SMEM>>>(qkv2, att2);

    // 4) output projection -> fp32 out
    mma_gemm<false><<<dim3(EMBED / BN, MROWS / BM), 256, GEMM_SMEM>>>(
        att2, wo2, b_out, out, EMBED);
}